// round 2
// baseline (speedup 1.0000x reference)
#include <cuda_runtime.h>
#include <cuda_bf16.h>
#include <cstddef>

// ---------------------------------------------------------------------------
// Problem constants
// ---------------------------------------------------------------------------
#define Bn   8
#define Cc   512
#define Nn   2304      // 48*48
#define C1n  256
#define C2n  256
#define CGn  128
#define Gg   4
#define OUTC 512
#define EPSf 1e-5f
#define SCALEf (1.0f/16.0f)   // C1^-0.5 = 256^-0.5

// ---------------------------------------------------------------------------
// Scratch (device globals: allocation-free per harness rules)
// ---------------------------------------------------------------------------
// PROJ[t][g][b][256][N], t in {0:theta, 1:phi, 2:g}
__device__ float g_PROJ[(size_t)3 * Gg * Bn * C1n * Nn];     // 226 MB
// A[b][N][N] : attention probs for ONE stage at a time (stages looped)
__device__ float g_A[(size_t)Bn * Nn * Nn];                  // 170 MB
// Y[g][b][256][N]
__device__ float g_Y[(size_t)Gg * Bn * C2n * Nn];            // 75.5 MB
// PR[b][512][n] : W-conv outputs laid out in final concat channel order
__device__ float g_PR[(size_t)Bn * (Gg * CGn) * Nn];         // 37.7 MB
// BN statistics + folded params
__device__ float g_mean1[512], g_var1[512];
__device__ float g_mean2[512], g_var2[512];
__device__ float g_tc[512];        // BN fold: additive term per pr channel
__device__ float g_ws[1024];       // per-k column scale for bottleneck GEMM
__device__ float g_const[512];     // folded bias for bottleneck GEMM

// ---------------------------------------------------------------------------
// Generic tiled SGEMM body: C[o, n] = sum_k W[o,k] * X[k,n] + bias[o]
// BM=BN=64, BK=16, 256 threads, 4x4 per thread.
// W row-major with leading dim K, X row-major with leading dim Nn.
// ---------------------------------------------------------------------------
__device__ __forceinline__ void gemm_body(const float* __restrict__ W,
                                          const float* __restrict__ X,
                                          const float* __restrict__ bias,
                                          float* __restrict__ Cp, int K)
{
    __shared__ float Ws[16][68];   // [k][o], padded
    __shared__ float Xs[16][64];   // [k][n]
    const int t  = threadIdx.x;
    const int n0 = blockIdx.x * 64;
    const int o0 = blockIdx.y * 64;
    const int tx = t & 15, ty = t >> 4;
    const int wrow = t >> 2, wc4 = t & 3;    // W tile loads
    const int xrow = t >> 4, xc4 = t & 15;   // X tile loads

    float acc[4][4] = {};
    for (int k0 = 0; k0 < K; k0 += 16) {
        float4 wv = *(const float4*)&W[(size_t)(o0 + wrow) * K + k0 + wc4 * 4];
        float4 xv = *(const float4*)&X[(size_t)(k0 + xrow) * Nn + n0 + xc4 * 4];
        __syncthreads();
        Ws[wc4 * 4 + 0][wrow] = wv.x;
        Ws[wc4 * 4 + 1][wrow] = wv.y;
        Ws[wc4 * 4 + 2][wrow] = wv.z;
        Ws[wc4 * 4 + 3][wrow] = wv.w;
        *(float4*)&Xs[xrow][xc4 * 4] = xv;
        __syncthreads();
#pragma unroll
        for (int kk = 0; kk < 16; kk++) {
            float4 a4 = *(const float4*)&Ws[kk][ty * 4];
            float4 b4 = *(const float4*)&Xs[kk][tx * 4];
            float a[4] = {a4.x, a4.y, a4.z, a4.w};
            float b[4] = {b4.x, b4.y, b4.z, b4.w};
#pragma unroll
            for (int j = 0; j < 4; j++)
#pragma unroll
                for (int i = 0; i < 4; i++)
                    acc[j][i] += a[j] * b[i];
        }
    }
#pragma unroll
    for (int j = 0; j < 4; j++) {
        float bb = bias ? bias[o0 + ty * 4 + j] : 0.0f;
#pragma unroll
        for (int i = 0; i < 4; i++)
            Cp[(size_t)(o0 + ty * 4 + j) * Nn + n0 + tx * 4 + i] = acc[j][i] + bb;
    }
}

// ---------------------------------------------------------------------------
// K1: projections.  grid (36, 4, 32=G*B).  t selects theta/phi/g.
// ---------------------------------------------------------------------------
__global__ __launch_bounds__(256) void k_proj(const float* __restrict__ W,
                                              const float* __restrict__ bias,
                                              const float* __restrict__ feats,
                                              int t)
{
    const int g = blockIdx.z >> 3, b = blockIdx.z & 7;
    const float* Wp = W + (size_t)g * C1n * Cc;
    const float* bp = bias + (size_t)g * C1n;
    const float* Xp = feats + (size_t)b * Cc * Nn;
    float* Cp = g_PROJ + ((size_t)(t * Gg + g) * Bn + b) * C1n * Nn;
    gemm_body(Wp, Xp, bp, Cp, Cc);
}

// ---------------------------------------------------------------------------
// K2: scores + softmax for stage g.  grid (144, 8), 256 threads,
// dynamic smem: th tile (256x16) + score rows (16x2304).
// Each block: 16 query rows, full 2304-key score row kept in smem.
// ---------------------------------------------------------------------------
#define ATTN_SMEM ((256 * 16 + 16 * Nn) * 4)

__global__ __launch_bounds__(256) void k_attn(int g)
{
    extern __shared__ float sm[];
    float* th_s = sm;              // [c*16 + mi]
    float* s_s  = sm + 256 * 16;   // [mi*Nn + n]

    const int t  = threadIdx.x;
    const int m0 = blockIdx.x * 16;
    const int b  = blockIdx.y;
    const float* TH = g_PROJ + ((size_t)(0 * Gg + g) * Bn + b) * C1n * Nn;
    const float* PH = g_PROJ + ((size_t)(1 * Gg + g) * Bn + b) * C1n * Nn;

    // load theta tile: th_s[c][mi] = TH[c, m0+mi]
    for (int i = t; i < 256 * 16; i += 256) {
        int c = i >> 4, mi = i & 15;
        th_s[i] = TH[(size_t)c * Nn + m0 + mi];
    }
    __syncthreads();

    // scores: thread owns one key column per 256-wide chunk
    for (int nb = 0; nb < Nn / 256; nb++) {
        const int n = nb * 256 + t;
        float acc[16] = {};
#pragma unroll 4
        for (int c = 0; c < 256; c++) {
            float ph = PH[(size_t)c * Nn + n];
            float4 t0 = *(const float4*)&th_s[c * 16 + 0];
            float4 t1 = *(const float4*)&th_s[c * 16 + 4];
            float4 t2 = *(const float4*)&th_s[c * 16 + 8];
            float4 t3 = *(const float4*)&th_s[c * 16 + 12];
            acc[0]  += t0.x * ph; acc[1]  += t0.y * ph; acc[2]  += t0.z * ph; acc[3]  += t0.w * ph;
            acc[4]  += t1.x * ph; acc[5]  += t1.y * ph; acc[6]  += t1.z * ph; acc[7]  += t1.w * ph;
            acc[8]  += t2.x * ph; acc[9]  += t2.y * ph; acc[10] += t2.z * ph; acc[11] += t2.w * ph;
            acc[12] += t3.x * ph; acc[13] += t3.y * ph; acc[14] += t3.z * ph; acc[15] += t3.w * ph;
        }
#pragma unroll
        for (int mi = 0; mi < 16; mi++)
            s_s[mi * Nn + n] = acc[mi] * SCALEf;
    }
    __syncthreads();

    // softmax: warp w handles rows w and w+8
    const int w = t >> 5, lane = t & 31;
    for (int mi = w; mi < 16; mi += 8) {
        float* row = s_s + mi * Nn;
        float mx = -1e30f;
        for (int j = lane; j < Nn; j += 32) mx = fmaxf(mx, row[j]);
#pragma unroll
        for (int off = 16; off; off >>= 1) mx = fmaxf(mx, __shfl_xor_sync(0xffffffffu, mx, off));
        float sum = 0.0f;
        for (int j = lane; j < Nn; j += 32) {
            float e = __expf(row[j] - mx);
            row[j] = e;
            sum += e;
        }
#pragma unroll
        for (int off = 16; off; off >>= 1) sum += __shfl_xor_sync(0xffffffffu, sum, off);
        float inv = 1.0f / sum;
        float* Arow = g_A + ((size_t)b * Nn + (m0 + mi)) * Nn;
        for (int j = lane; j < Nn; j += 32) Arow[j] = row[j] * inv;
    }
}

// ---------------------------------------------------------------------------
// K3: Y[c,m] = sum_n GX[c,n] * A[m,n]   (NT GEMM, both K-contiguous)
// grid (36=m, 4=c, 8=b), BK=32
// ---------------------------------------------------------------------------
__global__ __launch_bounds__(256) void k_av(int g)
{
    __shared__ float Gs[32][68];   // [k][c]
    __shared__ float As[32][68];   // [k][m]
    const int t  = threadIdx.x;
    const int m0 = blockIdx.x * 64;
    const int c0 = blockIdx.y * 64;
    const int b  = blockIdx.z;
    const float* GX   = g_PROJ + ((size_t)(2 * Gg + g) * Bn + b) * C2n * Nn;
    const float* Amat = g_A + (size_t)b * Nn * Nn;
    float* Yp = g_Y + ((size_t)g * Bn + b) * C2n * Nn;
    const int tx = t & 15, ty = t >> 4;

    float acc[4][4] = {};
    for (int k0 = 0; k0 < Nn; k0 += 32) {
        float4 gv[2], av[2];
#pragma unroll
        for (int l = 0; l < 2; l++) {
            int lin = t + 256 * l;
            int row = lin >> 3, c4 = lin & 7;
            gv[l] = *(const float4*)&GX[(size_t)(c0 + row) * Nn + k0 + c4 * 4];
            av[l] = *(const float4*)&Amat[(size_t)(m0 + row) * Nn + k0 + c4 * 4];
        }
        __syncthreads();
#pragma unroll
        for (int l = 0; l < 2; l++) {
            int lin = t + 256 * l;
            int row = lin >> 3, c4 = lin & 7;
            Gs[c4 * 4 + 0][row] = gv[l].x; Gs[c4 * 4 + 1][row] = gv[l].y;
            Gs[c4 * 4 + 2][row] = gv[l].z; Gs[c4 * 4 + 3][row] = gv[l].w;
            As[c4 * 4 + 0][row] = av[l].x; As[c4 * 4 + 1][row] = av[l].y;
            As[c4 * 4 + 2][row] = av[l].z; As[c4 * 4 + 3][row] = av[l].w;
        }
        __syncthreads();
#pragma unroll
        for (int kk = 0; kk < 32; kk++) {
            float4 a4 = *(const float4*)&Gs[kk][ty * 4];
            float4 b4 = *(const float4*)&As[kk][tx * 4];
            float a[4] = {a4.x, a4.y, a4.z, a4.w};
            float bb[4] = {b4.x, b4.y, b4.z, b4.w};
#pragma unroll
            for (int j = 0; j < 4; j++)
#pragma unroll
                for (int i = 0; i < 4; i++)
                    acc[j][i] += a[j] * bb[i];
        }
    }
#pragma unroll
    for (int j = 0; j < 4; j++)
#pragma unroll
        for (int i = 0; i < 4; i++)
            Yp[(size_t)(c0 + ty * 4 + j) * Nn + m0 + tx * 4 + i] = acc[j][i];
}

// ---------------------------------------------------------------------------
// K4: W-conv -> PR in final concat channel order. grid (36, 2, 32=G*B)
// ---------------------------------------------------------------------------
__global__ __launch_bounds__(256) void k_wy(const float* __restrict__ w_w,
                                            const float* __restrict__ w_b)
{
    const int g = blockIdx.z >> 3, b = blockIdx.z & 7;
    const float* Wp = w_w + (size_t)g * CGn * C2n;
    const float* bp = w_b + (size_t)g * CGn;
    const float* Xp = g_Y + ((size_t)g * Bn + b) * C2n * Nn;
    float* Cp = g_PR + (size_t)b * 512 * Nn + (size_t)g * CGn * Nn;
    gemm_body(Wp, Xp, bp, Cp, C2n);
}

// ---------------------------------------------------------------------------
// K5/K8: BN statistics over (B, N) per channel. which=0 -> PR/mean1,
// which=1 -> X(d_out)/mean2. grid 512 blocks x 256 threads.
// ---------------------------------------------------------------------------
__global__ void k_bnstats(const float* __restrict__ Xarg, int which)
{
    const float* X = (which == 0) ? g_PR : Xarg;
    float* meanp = (which == 0) ? g_mean1 : g_mean2;
    float* varp  = (which == 0) ? g_var1  : g_var2;
    const int ch = blockIdx.x, t = threadIdx.x;
    double s = 0.0, s2 = 0.0;
    for (int i = t; i < Bn * Nn; i += 256) {
        int b = i / Nn, n = i - b * Nn;
        float v = X[((size_t)b * 512 + ch) * Nn + n];
        s += v; s2 += (double)v * v;
    }
    __shared__ double sh0[256], sh1[256];
    sh0[t] = s; sh1[t] = s2;
    __syncthreads();
    for (int o = 128; o > 0; o >>= 1) {
        if (t < o) { sh0[t] += sh0[t + o]; sh1[t] += sh1[t + o]; }
        __syncthreads();
    }
    if (t == 0) {
        double cnt = (double)Bn * Nn;
        double m = sh0[0] / cnt;
        meanp[ch] = (float)m;
        varp[ch] = (float)(sh1[0] / cnt - m * m);
    }
}

// K6: fold prior-BN into bottleneck weight column scales. 1 block, 1024 thr.
__global__ void k_prep1(const float* __restrict__ wg, const float* __restrict__ wb)
{
    int c = threadIdx.x;
    if (c < 512) {
        float sv = wg[c] * rsqrtf(g_var1[c] + EPSf);
        g_tc[c] = wb[c] - g_mean1[c] * sv;
        g_ws[512 + c] = sv;
    } else {
        g_ws[c - 512] = 1.0f;
    }
}

// K7: folded constant bias: const[o] = bc_b[o] + sum_c bc_w[o,512+c]*t[c]
__global__ void k_prep2(const float* __restrict__ bc_w, const float* __restrict__ bc_b)
{
    int o = blockIdx.x * blockDim.x + threadIdx.x;
    float s = bc_b[o];
    for (int c = 0; c < 512; c++)
        s += bc_w[(size_t)o * 1024 + 512 + c] * g_tc[c];
    g_const[o] = s;
}

// ---------------------------------------------------------------------------
// K9: bottleneck GEMM with dual X source + per-column weight scale + folded
// bias, writing straight to d_out in (b, o, n) layout. grid (36, 8, 8)
// ---------------------------------------------------------------------------
__global__ __launch_bounds__(256) void k_final(const float* __restrict__ bc_w,
                                               const float* __restrict__ feats,
                                               float* __restrict__ out)
{
    __shared__ float Ws[16][68];
    __shared__ float Xs[16][64];
    const int t  = threadIdx.x;
    const int n0 = blockIdx.x * 64;
    const int o0 = blockIdx.y * 64;
    const int b  = blockIdx.z;
    const float* X1 = feats + (size_t)b * Cc * Nn;
    const float* X2 = g_PR  + (size_t)b * 512 * Nn;
    float* Cp = out + (size_t)b * OUTC * Nn;
    const int tx = t & 15, ty = t >> 4;
    const int wrow = t >> 2, wc4 = t & 3;
    const int xrow = t >> 4, xc4 = t & 15;

    float acc[4][4] = {};
    for (int k0 = 0; k0 < 1024; k0 += 16) {
        float4 wv = *(const float4*)&bc_w[(size_t)(o0 + wrow) * 1024 + k0 + wc4 * 4];
        float4 sc = *(const float4*)&g_ws[k0 + wc4 * 4];
        wv.x *= sc.x; wv.y *= sc.y; wv.z *= sc.z; wv.w *= sc.w;
        const float* Xb = (k0 < 512) ? (X1 + (size_t)k0 * Nn) : (X2 + (size_t)(k0 - 512) * Nn);
        float4 xv = *(const float4*)&Xb[(size_t)xrow * Nn + n0 + xc4 * 4];
        __syncthreads();
        Ws[wc4 * 4 + 0][wrow] = wv.x;
        Ws[wc4 * 4 + 1][wrow] = wv.y;
        Ws[wc4 * 4 + 2][wrow] = wv.z;
        Ws[wc4 * 4 + 3][wrow] = wv.w;
        *(float4*)&Xs[xrow][xc4 * 4] = xv;
        __syncthreads();
#pragma unroll
        for (int kk = 0; kk < 16; kk++) {
            float4 a4 = *(const float4*)&Ws[kk][ty * 4];
            float4 b4 = *(const float4*)&Xs[kk][tx * 4];
            float a[4] = {a4.x, a4.y, a4.z, a4.w};
            float bb[4] = {b4.x, b4.y, b4.z, b4.w};
#pragma unroll
            for (int j = 0; j < 4; j++)
#pragma unroll
                for (int i = 0; i < 4; i++)
                    acc[j][i] += a[j] * bb[i];
        }
    }
#pragma unroll
    for (int j = 0; j < 4; j++) {
        float bb = g_const[o0 + ty * 4 + j];
#pragma unroll
        for (int i = 0; i < 4; i++)
            Cp[(size_t)(o0 + ty * 4 + j) * Nn + n0 + tx * 4 + i] = acc[j][i] + bb;
    }
}

// K10: final BN applied in place on d_out
__global__ void k_apply(float* __restrict__ out,
                        const float* __restrict__ gamma,
                        const float* __restrict__ beta)
{
    size_t idx = (size_t)blockIdx.x * blockDim.x + threadIdx.x;
    size_t total = (size_t)Bn * OUTC * Nn;
    if (idx >= total) return;
    int ch = (int)((idx / Nn) % OUTC);
    float v = out[idx];
    out[idx] = (v - g_mean2[ch]) * rsqrtf(g_var2[ch] + EPSf) * gamma[ch] + beta[ch];
}

// ---------------------------------------------------------------------------
// Launch
// ---------------------------------------------------------------------------
extern "C" void kernel_launch(void* const* d_in, const int* in_sizes, int n_in,
                              void* d_out, int out_size)
{
    const float* feats    = (const float*)d_in[0];
    const float* theta_w  = (const float*)d_in[1];
    const float* theta_b  = (const float*)d_in[2];
    const float* phi_w    = (const float*)d_in[3];
    const float* phi_b    = (const float*)d_in[4];
    const float* g_w      = (const float*)d_in[5];
    const float* g_b      = (const float*)d_in[6];
    const float* w_w      = (const float*)d_in[7];
    const float* w_b      = (const float*)d_in[8];
    const float* w_gamma  = (const float*)d_in[9];
    const float* w_beta   = (const float*)d_in[10];
    const float* bc_w     = (const float*)d_in[11];
    const float* bc_b     = (const float*)d_in[12];
    const float* bc_gamma = (const float*)d_in[13];
    const float* bc_beta  = (const float*)d_in[14];
    float* out = (float*)d_out;

    cudaFuncSetAttribute(k_attn, cudaFuncAttributeMaxDynamicSharedMemorySize, ATTN_SMEM);

    dim3 blk(256);
    // projections: theta, phi, g
    k_proj<<<dim3(Nn / 64, C1n / 64, Gg * Bn), blk>>>(theta_w, theta_b, feats, 0);
    k_proj<<<dim3(Nn / 64, C1n / 64, Gg * Bn), blk>>>(phi_w,   phi_b,   feats, 1);
    k_proj<<<dim3(Nn / 64, C1n / 64, Gg * Bn), blk>>>(g_w,     g_b,     feats, 2);

    // per-stage attention (A buffer reused, stream-ordered)
    for (int g = 0; g < Gg; g++) {
        k_attn<<<dim3(Nn / 16, Bn), blk, ATTN_SMEM>>>(g);
        k_av<<<dim3(Nn / 64, C2n / 64, Bn), blk>>>(g);
    }

    // W conv into concat layout
    k_wy<<<dim3(Nn / 64, CGn / 64, Gg * Bn), blk>>>(w_w, w_b);

    // prior BN stats + fold into bottleneck GEMM
    k_bnstats<<<512, 256>>>(nullptr, 0);
    k_prep1<<<1, 1024>>>(w_gamma, w_beta);
    k_prep2<<<2, 256>>>(bc_w, bc_b);

    // bottleneck GEMM straight into d_out
    k_final<<<dim3(Nn / 64, OUTC / 64, Bn), blk>>>(bc_w, feats, out);

    // output BN stats + in-place apply
    k_bnstats<<<512, 256>>>((const float*)out, 1);
    size_t total = (size_t)Bn * OUTC * Nn;
    k_apply<<<(unsigned)((total + 255) / 256), 256>>>(out, bc_gamma, bc_beta);
}